// round 3
// baseline (speedup 1.0000x reference)
#include <cuda_runtime.h>
#include <math.h>

#define DIM   768
#define HEADS 12
#define HD    64
#define B_    2
#define HH    48
#define WW    48
#define NTOK  (HH*WW)        // 2304
#define BHC   (B_*HEADS)     // 24
#define MROWS (B_*NTOK)      // 4608

// -------- scratch (device globals; no allocation allowed) --------
__device__ float g_q[BHC*NTOK*HD];   // [b,h,n,d]
__device__ float g_k[BHC*NTOK*HD];
__device__ float g_v[BHC*NTOK*HD];
__device__ float g_o[MROWS*DIM];     // [b,n, h*d]

// ====================================================================
// GEMM: C[M,N] = A[M,K] @ B[N,K]^T + bias[N]
// 128x128 tile, BK=8 double-buffered, 256 threads, 8x8 per thread.
// EPI==0: plain row-major write.
// EPI==1: QKV epilogue -> fused RoPE (on q,k) + scatter to [b,h,n,d].
// ====================================================================
template<int EPI>
__global__ void __launch_bounds__(256) gemm_kernel(
    const float* __restrict__ A, const float* __restrict__ Bm,
    const float* __restrict__ bias, float* __restrict__ C,
    int M, int N, int K)
{
    __shared__ __align__(16) float As[2][8][128];
    __shared__ __align__(16) float Bs[2][8][128];

    const int tid = threadIdx.x;
    const int ty = tid >> 4, tx = tid & 15;
    const int bm = blockIdx.y * 128, bn = blockIdx.x * 128;
    const int lrow = tid >> 1;           // 0..127
    const int lcg  = (tid & 1) * 4;      // 0 or 4

    float acc[8][8] = {};

    // prologue: load tile 0 into buffer 0
    {
        float4 av = *(const float4*)&A [(size_t)(bm + lrow) * K + lcg];
        float4 bv = *(const float4*)&Bm[(size_t)(bn + lrow) * K + lcg];
        As[0][lcg+0][lrow] = av.x; As[0][lcg+1][lrow] = av.y;
        As[0][lcg+2][lrow] = av.z; As[0][lcg+3][lrow] = av.w;
        Bs[0][lcg+0][lrow] = bv.x; Bs[0][lcg+1][lrow] = bv.y;
        Bs[0][lcg+2][lrow] = bv.z; Bs[0][lcg+3][lrow] = bv.w;
    }
    __syncthreads();

    int buf = 0;
    for (int k0 = 0; k0 < K; k0 += 8) {
        const bool more = (k0 + 8) < K;
        float4 av, bv;
        if (more) {
            av = *(const float4*)&A [(size_t)(bm + lrow) * K + k0 + 8 + lcg];
            bv = *(const float4*)&Bm[(size_t)(bn + lrow) * K + k0 + 8 + lcg];
        }

        #pragma unroll
        for (int kk = 0; kk < 8; kk++) {
            float4 a0 = *(const float4*)&As[buf][kk][ty*8];
            float4 a1 = *(const float4*)&As[buf][kk][ty*8+4];
            float4 b0 = *(const float4*)&Bs[buf][kk][tx*8];
            float4 b1 = *(const float4*)&Bs[buf][kk][tx*8+4];
            float a8[8] = {a0.x,a0.y,a0.z,a0.w,a1.x,a1.y,a1.z,a1.w};
            float b8[8] = {b0.x,b0.y,b0.z,b0.w,b1.x,b1.y,b1.z,b1.w};
            #pragma unroll
            for (int i = 0; i < 8; i++)
                #pragma unroll
                for (int j = 0; j < 8; j++)
                    acc[i][j] += a8[i] * b8[j];
        }

        if (more) {
            int nb = buf ^ 1;
            As[nb][lcg+0][lrow] = av.x; As[nb][lcg+1][lrow] = av.y;
            As[nb][lcg+2][lrow] = av.z; As[nb][lcg+3][lrow] = av.w;
            Bs[nb][lcg+0][lrow] = bv.x; Bs[nb][lcg+1][lrow] = bv.y;
            Bs[nb][lcg+2][lrow] = bv.z; Bs[nb][lcg+3][lrow] = bv.w;
        }
        __syncthreads();
        buf ^= 1;
    }

    if (EPI == 0) {
        #pragma unroll
        for (int i = 0; i < 8; i++) {
            int m = bm + ty*8 + i;
            #pragma unroll
            for (int j = 0; j < 8; j++) {
                int c = bn + tx*8 + j;
                C[(size_t)m * N + c] = acc[i][j] + bias[c];
            }
        }
    } else {
        // QKV epilogue with fused RoPE.
        // Pair column for RoPE is c ^ 32 -> owned by lane (tx^4) in same warp.
        #pragma unroll
        for (int i = 0; i < 8; i++) {
            int m = bm + ty*8 + i;
            int b = m / NTOK;
            int pos = m - b * NTOK;
            int ypix = pos / WW, xpix = pos - ypix * WW;

            float val[8];
            #pragma unroll
            for (int j = 0; j < 8; j++)
                val[j] = acc[i][j] + bias[bn + tx*8 + j];
            float pairv[8];
            #pragma unroll
            for (int j = 0; j < 8; j++)
                pairv[j] = __shfl_xor_sync(0xffffffffu, val[j], 4);

            #pragma unroll
            for (int j = 0; j < 8; j++) {
                int c = bn + tx*8 + j;
                int which = c / DIM;
                int rem = c - which * DIM;
                int h = rem >> 6;
                int d = rem & 63;
                float outv = val[j];
                if (which < 2) {
                    int p    = d & 15;
                    int axis = (d >> 4) & 1;
                    float idxf  = axis ? (float)xpix : (float)ypix;
                    float coord = 2.0f * ((idxf + 0.5f) / 48.0f) - 1.0f;
                    // invperiod = 100^(-p/16) = exp2(-p * log2(100)/16)
                    float invp = exp2f(-(float)p * 0.41524101186092607f);
                    float ang = 6.283185307179586f * coord * invp;
                    float sn, cs;
                    sincosf(ang, &sn, &cs);
                    outv = (d & 32) ? (val[j]*cs + pairv[j]*sn)
                                    : (val[j]*cs - pairv[j]*sn);
                }
                float* dst = (which == 0) ? g_q : (which == 1) ? g_k : g_v;
                dst[((size_t)(b*HEADS + h) * NTOK + pos) * HD + d] = outv;
            }
        }
    }
}

// ====================================================================
// Flash-style fp32 attention, v2.
// Grid: (NTOK/128, BHC). Block: 256 threads.
// CTA: 128 query rows, key tiles of 64, online softmax.
// Thread (ty=tid/8 in 0..31, tx=tid%8): 4 rows x 8 cols for S and O.
// Smem (dynamic, 100KB): transposed layouts for broadcast-friendly float4.
//   Qs_t[64][132]  (d-major, 128 rows)
//   Ks_t[64][68]   (d-major, 64 keys)
//   Vs  [64][68]   (natural)
//   Ps_t[64][132]  (k-major, 128 rows)
// ====================================================================
#define QS_OFF 0
#define KS_OFF (64*132)
#define VS_OFF (KS_OFF + 64*68)
#define PS_OFF (VS_OFF + 64*68)
#define ATTN_SMEM_FLOATS (PS_OFF + 64*132)
#define ATTN_SMEM_BYTES  (ATTN_SMEM_FLOATS * 4)

__global__ void __launch_bounds__(256, 2) attn_kernel()
{
    extern __shared__ __align__(16) float sm[];
    float* Qs = sm + QS_OFF;   // [d][row], stride 132
    float* Ks = sm + KS_OFF;   // [d][key], stride 68
    float* Vs = sm + VS_OFF;   // [key][d], stride 68
    float* Ps = sm + PS_OFF;   // [key][row], stride 132

    const int tid = threadIdx.x;
    const int ty = tid >> 3;      // 0..31
    const int tx = tid & 7;       // 0..7
    const int ty4 = ty * 4;
    const int tx8 = tx * 8;
    const int bh = blockIdx.y;
    const int q0 = blockIdx.x * 128;

    const float* Qg = g_q + ((size_t)bh * NTOK + q0) * HD;
    const float* Kg = g_k + (size_t)bh * NTOK * HD;
    const float* Vg = g_v + (size_t)bh * NTOK * HD;

    // load Q tile (128 x 64), transposed into Qs[d][row]
    #pragma unroll
    for (int t = 0; t < 8; t++) {
        int lin = t * 256 + tid;
        int row = lin >> 4, g = (lin & 15) * 4;
        float4 v = *(const float4*)&Qg[(size_t)row * HD + g];
        Qs[(g+0)*132 + row] = v.x; Qs[(g+1)*132 + row] = v.y;
        Qs[(g+2)*132 + row] = v.z; Qs[(g+3)*132 + row] = v.w;
    }

    float o[4][8] = {};
    float mi[4], li[4];
    #pragma unroll
    for (int i = 0; i < 4; i++) { mi[i] = -1e30f; li[i] = 0.0f; }
    const float scale = 0.125f;   // 1/sqrt(64)

    for (int k0 = 0; k0 < NTOK; k0 += 64) {
        // global loads for this tile (4 float4 each of K and V per thread)
        float4 kr[4], vr[4];
        #pragma unroll
        for (int t = 0; t < 4; t++) {
            int lin = t * 256 + tid;
            int row = lin >> 4, g = (lin & 15) * 4;
            kr[t] = *(const float4*)&Kg[(size_t)(k0 + row) * HD + g];
            vr[t] = *(const float4*)&Vg[(size_t)(k0 + row) * HD + g];
        }
        __syncthreads();   // prev-iter readers of Ks/Vs/Ps done (also covers Q on iter 0)
        #pragma unroll
        for (int t = 0; t < 4; t++) {
            int lin = t * 256 + tid;
            int row = lin >> 4, g = (lin & 15) * 4;
            Ks[(g+0)*68 + row] = kr[t].x; Ks[(g+1)*68 + row] = kr[t].y;
            Ks[(g+2)*68 + row] = kr[t].z; Ks[(g+3)*68 + row] = kr[t].w;
            *(float4*)&Vs[row*68 + g] = vr[t];
        }
        __syncthreads();

        // S = Q @ K^T  (128 x 64); thread: 4 rows x 8 cols
        float s[4][8] = {};
        #pragma unroll 8
        for (int d = 0; d < 64; d++) {
            float4 q4 = *(const float4*)&Qs[d*132 + ty4];
            float4 k0v = *(const float4*)&Ks[d*68 + tx8];
            float4 k1v = *(const float4*)&Ks[d*68 + tx8 + 4];
            float qv[4] = {q4.x, q4.y, q4.z, q4.w};
            float kv[8] = {k0v.x,k0v.y,k0v.z,k0v.w,k1v.x,k1v.y,k1v.z,k1v.w};
            #pragma unroll
            for (int i = 0; i < 4; i++)
                #pragma unroll
                for (int j = 0; j < 8; j++)
                    s[i][j] += qv[i] * kv[j];
        }

        // online softmax (reduce over tx group of 8 lanes)
        #pragma unroll
        for (int i = 0; i < 4; i++) {
            float rm = -1e30f;
            #pragma unroll
            for (int j = 0; j < 8; j++) { s[i][j] *= scale; rm = fmaxf(rm, s[i][j]); }
            #pragma unroll
            for (int off = 1; off < 8; off <<= 1)
                rm = fmaxf(rm, __shfl_xor_sync(0xffffffffu, rm, off));
            float nm = fmaxf(mi[i], rm);
            float rs = 0.0f;
            #pragma unroll
            for (int j = 0; j < 8; j++) { s[i][j] = __expf(s[i][j] - nm); rs += s[i][j]; }
            #pragma unroll
            for (int off = 1; off < 8; off <<= 1)
                rs += __shfl_xor_sync(0xffffffffu, rs, off);
            float f = __expf(mi[i] - nm);
            li[i] = li[i] * f + rs;
            mi[i] = nm;
            #pragma unroll
            for (int j = 0; j < 8; j++) o[i][j] *= f;
        }
        // write P transposed: Ps[key][row], one float4 (4 rows) per col
        #pragma unroll
        for (int c = 0; c < 8; c++) {
            float4 pv = make_float4(s[0][c], s[1][c], s[2][c], s[3][c]);
            *(float4*)&Ps[(tx8 + c)*132 + ty4] = pv;
        }
        __syncthreads();

        // O += P @ V  (128 x 64); thread: 4 rows x 8 cols
        #pragma unroll 8
        for (int k = 0; k < 64; k++) {
            float4 p4 = *(const float4*)&Ps[k*132 + ty4];
            float4 v0 = *(const float4*)&Vs[k*68 + tx8];
            float4 v1 = *(const float4*)&Vs[k*68 + tx8 + 4];
            float pv[4] = {p4.x, p4.y, p4.z, p4.w};
            float vv[8] = {v0.x,v0.y,v0.z,v0.w,v1.x,v1.y,v1.z,v1.w};
            #pragma unroll
            for (int i = 0; i < 4; i++)
                #pragma unroll
                for (int j = 0; j < 8; j++)
                    o[i][j] += pv[i] * vv[j];
        }
    }

    // write O (normalized) to g_o in [b, n, h*d] layout
    int b = bh / HEADS, h = bh - b * HEADS;
    #pragma unroll
    for (int i = 0; i < 4; i++) {
        int pos = q0 + ty4 + i;
        float inv = 1.0f / li[i];
        float* dst = &g_o[((size_t)(b*NTOK + pos)) * DIM + h*HD + tx8];
        float4 o0 = make_float4(o[i][0]*inv, o[i][1]*inv, o[i][2]*inv, o[i][3]*inv);
        float4 o1 = make_float4(o[i][4]*inv, o[i][5]*inv, o[i][6]*inv, o[i][7]*inv);
        *(float4*)&dst[0] = o0;
        *(float4*)&dst[4] = o1;
    }
}

// ====================================================================
// launcher
// ====================================================================
extern "C" void kernel_launch(void* const* d_in, const int* in_sizes, int n_in,
                              void* d_out, int out_size)
{
    const float* x      = (const float*)d_in[0];
    const float* w_qkv  = (const float*)d_in[1];
    const float* b_qkv  = (const float*)d_in[2];
    const float* w_proj = (const float*)d_in[3];
    const float* b_proj = (const float*)d_in[4];
    float* out = (float*)d_out;

    void* p_go = nullptr;
    cudaGetSymbolAddress(&p_go, g_o);

    static bool attr_set = false;
    if (!attr_set) {
        cudaFuncSetAttribute(attn_kernel,
                             cudaFuncAttributeMaxDynamicSharedMemorySize,
                             ATTN_SMEM_BYTES);
        attr_set = true;
    }

    // 1) QKV GEMM + bias + fused RoPE, scatter to [b,h,n,d] Q/K/V
    gemm_kernel<1><<<dim3(3*DIM/128, MROWS/128), 256>>>(
        x, w_qkv, b_qkv, nullptr, MROWS, 3*DIM, DIM);

    // 2) attention
    attn_kernel<<<dim3(NTOK/128, BHC), 256, ATTN_SMEM_BYTES>>>();

    // 3) output projection -> d_out
    gemm_kernel<0><<<dim3(DIM/128, MROWS/128), 256>>>(
        (const float*)p_go, w_proj, b_proj, out, MROWS, DIM, DIM);
}

// round 5
// speedup vs baseline: 1.2449x; 1.2449x over previous
#include <cuda_runtime.h>
#include <cuda_bf16.h>
#include <math.h>
#include <stdint.h>

#define DIM   768
#define HEADS 12
#define HD    64
#define B_    2
#define WW    48
#define NTOK  2304
#define BHC   24
#define MROWS 4608

// -------- scratch (device globals; no allocation allowed) --------
__device__ float g_q[BHC*NTOK*HD];
__device__ float g_k[BHC*NTOK*HD];
__device__ float g_v[BHC*NTOK*HD];
__device__ __nv_bfloat16 g_xh[MROWS*DIM],  g_xl[MROWS*DIM];
__device__ __nv_bfloat16 g_wqh[3*DIM*DIM], g_wql[3*DIM*DIM];
__device__ __nv_bfloat16 g_wph[DIM*DIM],   g_wpl[DIM*DIM];
__device__ __nv_bfloat16 g_ohh[MROWS*DIM], g_oll[MROWS*DIM];
__device__ float g_sin[NTOK*32], g_cos[NTOK*32];

// ==================== helpers ====================
__device__ __forceinline__ uint32_t smem_u32(const void* p) {
    uint32_t a;
    asm("{ .reg .u64 t; cvta.to.shared.u64 t, %1; cvt.u32.u64 %0, t; }" : "=r"(a) : "l"(p));
    return a;
}
__device__ __forceinline__ void ldsm4(uint32_t* r, uint32_t addr) {
    asm volatile("ldmatrix.sync.aligned.m8n8.x4.shared.b16 {%0,%1,%2,%3}, [%4];"
                 : "=r"(r[0]), "=r"(r[1]), "=r"(r[2]), "=r"(r[3]) : "r"(addr));
}
__device__ __forceinline__ void mma16816(float* d, const uint32_t* a,
                                         uint32_t b0, uint32_t b1) {
    asm volatile(
        "mma.sync.aligned.m16n8k16.row.col.f32.bf16.bf16.f32 "
        "{%0,%1,%2,%3}, {%4,%5,%6,%7}, {%8,%9}, {%0,%1,%2,%3};"
        : "+f"(d[0]), "+f"(d[1]), "+f"(d[2]), "+f"(d[3])
        : "r"(a[0]), "r"(a[1]), "r"(a[2]), "r"(a[3]), "r"(b0), "r"(b1));
}

// ==================== prep kernels ====================
__global__ void __launch_bounds__(256) split_kernel(
    const float* __restrict__ src, __nv_bfloat16* __restrict__ hi,
    __nv_bfloat16* __restrict__ lo, int n4)
{
    int i = blockIdx.x * 256 + threadIdx.x;
    if (i >= n4) return;
    float4 v = ((const float4*)src)[i];
    float f[4] = {v.x, v.y, v.z, v.w};
    __nv_bfloat16 h[4], l[4];
    #pragma unroll
    for (int j = 0; j < 4; j++) {
        h[j] = __float2bfloat16(f[j]);
        l[j] = __float2bfloat16(f[j] - __bfloat162float(h[j]));
    }
    ((__nv_bfloat162*)hi)[2*i]   = __halves2bfloat162(h[0], h[1]);
    ((__nv_bfloat162*)hi)[2*i+1] = __halves2bfloat162(h[2], h[3]);
    ((__nv_bfloat162*)lo)[2*i]   = __halves2bfloat162(l[0], l[1]);
    ((__nv_bfloat162*)lo)[2*i+1] = __halves2bfloat162(l[2], l[3]);
}

__global__ void __launch_bounds__(256) rope_tab_kernel()
{
    int idx = blockIdx.x * 256 + threadIdx.x;
    if (idx >= NTOK * 32) return;
    int n = idx >> 5, j = idx & 31;
    int axis = j >> 4, p = j & 15;
    int y = n / WW, x = n - y * WW;
    float idxf  = axis ? (float)x : (float)y;
    float coord = 2.0f * ((idxf + 0.5f) / 48.0f) - 1.0f;
    float invp  = exp2f(-(float)p * 0.41524101186092607f);  // 100^(-p/16)
    float sn, cs; sincosf(6.283185307179586f * coord * invp, &sn, &cs);
    g_sin[idx] = sn; g_cos[idx] = cs;
}

// ==================== mma.sync bf16-split GEMM ====================
// C[M,N] = (Ah+Al)[M,K] @ (Bh+Bl)[N,K]^T + bias   (lo*lo dropped)
// CTA 128x128, BK=32 double-buffered, 8 warps: warp_m=wid&3 (32 rows),
// warp_n=wid>>2 (64 cols). Warp tile 32x64 -> acc[2 mt][8 nt][4].
// Smem tiles padded to 40 bf16/row (80B): conflict-free ldmatrix.
#define TSTRIDE 40
#define TILE_E  (128*TSTRIDE)
#define GEMM_SMEM_B (8*TILE_E*2)   // 81920 bytes

__device__ __forceinline__ void g2r(uint4* r,
    const __nv_bfloat16* Ah, const __nv_bfloat16* Al,
    const __nv_bfloat16* Bh, const __nv_bfloat16* Bl,
    int bm, int bn, int K, int k0, int tid)
{
    #pragma unroll
    for (int p = 0; p < 2; p++) {
        int id = p * 256 + tid;
        int row = id >> 2, kc = id & 3;
        size_t oA = (size_t)(bm + row) * K + k0 + kc * 8;
        size_t oB = (size_t)(bn + row) * K + k0 + kc * 8;
        r[0+p] = *(const uint4*)&Ah[oA];
        r[2+p] = *(const uint4*)&Al[oA];
        r[4+p] = *(const uint4*)&Bh[oB];
        r[6+p] = *(const uint4*)&Bl[oB];
    }
}
__device__ __forceinline__ void r2s(__nv_bfloat16* sm, const uint4* r,
                                    int tid, int st)
{
    // layout: tiles [Ah, Al, Bh, Bl] for stage st at (st*4 + tile)*TILE_E
    #pragma unroll
    for (int p = 0; p < 2; p++) {
        int id = p * 256 + tid;
        int off = (id >> 2) * TSTRIDE + (id & 3) * 8;
        #pragma unroll
        for (int t = 0; t < 4; t++)
            *(uint4*)&sm[(st*4 + t) * TILE_E + off] = r[t*2 + p];
    }
}

template<int EPI>
__global__ void __launch_bounds__(256, 1) gemm_mma(
    const __nv_bfloat16* __restrict__ Ah, const __nv_bfloat16* __restrict__ Al,
    const __nv_bfloat16* __restrict__ Bh, const __nv_bfloat16* __restrict__ Bl,
    const float* __restrict__ bias, float* __restrict__ C, int M, int N, int K)
{
    extern __shared__ __align__(16) __nv_bfloat16 sm[];
    const uint32_t sbase = smem_u32(sm);
    const int tid = threadIdx.x;
    const int lane = tid & 31, wid = tid >> 5;
    const int wm = wid & 3, wn = wid >> 2;
    const int bm = blockIdx.y * 128, bn = blockIdx.x * 128;
    const int piece = lane >> 3, pr = lane & 7;

    float acc[2][8][4];
    #pragma unroll
    for (int i = 0; i < 2; i++)
        #pragma unroll
        for (int j = 0; j < 8; j++)
            #pragma unroll
            for (int k = 0; k < 4; k++) acc[i][j][k] = 0.0f;

    const int nit = K >> 5;     // 24
    uint4 r[8];
    g2r(r, Ah, Al, Bh, Bl, bm, bn, K, 0, tid);
    r2s(sm, r, tid, 0);
    __syncthreads();

    // ldmatrix lane row offsets (element units within a tile)
    // A: row = wm*32 + mt*16 + (piece&1)*8 + pr ; koff = ks*16 + (piece>>1)*8
    // B: row = wn*64 + np*16 + (piece&1)*8 + pr ; same koff
    const int arow = wm*32 + (piece & 1)*8 + pr;
    const int brow = wn*64 + (piece & 1)*8 + pr;
    const int kofp = (piece >> 1) * 8;

    for (int it = 0; it < nit; it++) {
        int st = it & 1;
        bool more = (it + 1) < nit;
        if (more) g2r(r, Ah, Al, Bh, Bl, bm, bn, K, (it + 1) << 5, tid);

        uint32_t tA = sbase + (uint32_t)(st*4) * (TILE_E*2);
        #pragma unroll
        for (int ks = 0; ks < 2; ks++) {
            int koff = ks*16 + kofp;
            uint32_t ah[2][4], al[2][4];
            #pragma unroll
            for (int mt = 0; mt < 2; mt++) {
                uint32_t ad = tA + ((arow + mt*16) * TSTRIDE + koff) * 2;
                ldsm4(ah[mt], ad);
                ldsm4(al[mt], ad + TILE_E*2);
            }
            #pragma unroll
            for (int np = 0; np < 4; np++) {
                uint32_t bd = tA + 2*(TILE_E*2)
                            + ((brow + np*16) * TSTRIDE + koff) * 2;
                uint32_t bh[4], bl[4];
                ldsm4(bh, bd);
                ldsm4(bl, bd + TILE_E*2);
                #pragma unroll
                for (int mt = 0; mt < 2; mt++) {
                    mma16816(acc[mt][np*2],   ah[mt], bh[0], bh[2]);
                    mma16816(acc[mt][np*2+1], ah[mt], bh[1], bh[3]);
                    mma16816(acc[mt][np*2],   ah[mt], bl[0], bl[2]);
                    mma16816(acc[mt][np*2+1], ah[mt], bl[1], bl[3]);
                    mma16816(acc[mt][np*2],   al[mt], bh[0], bh[2]);
                    mma16816(acc[mt][np*2+1], al[mt], bh[1], bh[3]);
                }
            }
        }
        __syncthreads();
        if (more) {
            r2s(sm, r, tid, st ^ 1);
            __syncthreads();
        }
    }

    // -------- epilogue --------
    const int cbase = bn + wn * 64;
    if (EPI == 0) {
        #pragma unroll
        for (int mt = 0; mt < 2; mt++)
            #pragma unroll
            for (int half = 0; half < 2; half++) {
                int m = bm + wm*32 + mt*16 + (lane >> 2) + half*8;
                #pragma unroll
                for (int nt = 0; nt < 8; nt++) {
                    int c = cbase + nt*8 + (lane & 3)*2;
                    float2 v;
                    v.x = acc[mt][nt][half*2+0] + bias[c];
                    v.y = acc[mt][nt][half*2+1] + bias[c+1];
                    *(float2*)&C[(size_t)m * N + c] = v;
                }
            }
    } else {
        int which = cbase / DIM;
        int h = (cbase % DIM) >> 6;
        float* base = (which == 0) ? g_q : (which == 1) ? g_k : g_v;
        #pragma unroll
        for (int mt = 0; mt < 2; mt++)
            #pragma unroll
            for (int half = 0; half < 2; half++) {
                int m = bm + wm*32 + mt*16 + (lane >> 2) + half*8;
                int bb = m / NTOK, pos = m - bb * NTOK;
                float* dst = base + ((size_t)(bb*HEADS + h) * NTOK + pos) * HD;
                if (which < 2) {
                    #pragma unroll
                    for (int nt = 0; nt < 4; nt++) {
                        int d0 = nt*8 + (lane & 3)*2;
                        float2 olo, ohi;
                        #pragma unroll
                        for (int j = 0; j < 2; j++) {
                            float vlo = acc[mt][nt][half*2+j]   + bias[cbase + d0 + j];
                            float vhi = acc[mt][nt+4][half*2+j] + bias[cbase + 32 + d0 + j];
                            float sn = g_sin[pos*32 + d0 + j];
                            float cs = g_cos[pos*32 + d0 + j];
                            float rl = vlo*cs - vhi*sn;
                            float rh = vhi*cs + vlo*sn;
                            if (j == 0) { olo.x = rl; ohi.x = rh; }
                            else        { olo.y = rl; ohi.y = rh; }
                        }
                        *(float2*)&dst[d0]      = olo;
                        *(float2*)&dst[32 + d0] = ohi;
                    }
                } else {
                    #pragma unroll
                    for (int nt = 0; nt < 8; nt++) {
                        int d = nt*8 + (lane & 3)*2;
                        float2 v;
                        v.x = acc[mt][nt][half*2+0] + bias[cbase + d];
                        v.y = acc[mt][nt][half*2+1] + bias[cbase + d + 1];
                        *(float2*)&dst[d] = v;
                    }
                }
            }
    }
}

// ==================== flash attention fp32 (bf16-split output) ====
#define QS_OFF 0
#define KS_OFF (64*132)
#define VS_OFF (KS_OFF + 64*68)
#define PS_OFF (VS_OFF + 64*68)
#define ATTN_SMEM_BYTES ((PS_OFF + 64*132) * 4)

__global__ void __launch_bounds__(256, 2) attn_kernel()
{
    extern __shared__ __align__(16) float smf[];
    float* Qs = smf + QS_OFF;
    float* Ks = smf + KS_OFF;
    float* Vs = smf + VS_OFF;
    float* Ps = smf + PS_OFF;

    const int tid = threadIdx.x;
    const int ty4 = (tid >> 3) * 4, tx8 = (tid & 7) * 8;
    const int bh = blockIdx.y, q0 = blockIdx.x * 128;

    const float* Qg = g_q + ((size_t)bh * NTOK + q0) * HD;
    const float* Kg = g_k + (size_t)bh * NTOK * HD;
    const float* Vg = g_v + (size_t)bh * NTOK * HD;

    #pragma unroll
    for (int t = 0; t < 8; t++) {
        int lin = t * 256 + tid;
        int row = lin >> 4, g = (lin & 15) * 4;
        float4 v = *(const float4*)&Qg[(size_t)row * HD + g];
        Qs[(g+0)*132 + row] = v.x; Qs[(g+1)*132 + row] = v.y;
        Qs[(g+2)*132 + row] = v.z; Qs[(g+3)*132 + row] = v.w;
    }

    float o[4][8] = {};
    float mi[4], li[4];
    #pragma unroll
    for (int i = 0; i < 4; i++) { mi[i] = -1e30f; li[i] = 0.0f; }
    const float scale = 0.125f;

    for (int k0 = 0; k0 < NTOK; k0 += 64) {
        float4 kr[4], vr[4];
        #pragma unroll
        for (int t = 0; t < 4; t++) {
            int lin = t * 256 + tid;
            int row = lin >> 4, g = (lin & 15) * 4;
            kr[t] = *(const float4*)&Kg[(size_t)(k0 + row) * HD + g];
            vr[t] = *(const float4*)&Vg[(size_t)(k0 + row) * HD + g];
        }
        __syncthreads();
        #pragma unroll
        for (int t = 0; t < 4; t++) {
            int lin = t * 256 + tid;
            int row = lin >> 4, g = (lin & 15) * 4;
            Ks[(g+0)*68 + row] = kr[t].x; Ks[(g+1)*68 + row] = kr[t].y;
            Ks[(g+2)*68 + row] = kr[t].z; Ks[(g+3)*68 + row] = kr[t].w;
            *(float4*)&Vs[row*68 + g] = vr[t];
        }
        __syncthreads();

        float s[4][8] = {};
        #pragma unroll 8
        for (int d = 0; d < 64; d++) {
            float4 q4 = *(const float4*)&Qs[d*132 + ty4];
            float4 k0v = *(const float4*)&Ks[d*68 + tx8];
            float4 k1v = *(const float4*)&Ks[d*68 + tx8 + 4];
            float qv[4] = {q4.x, q4.y, q4.z, q4.w};
            float kv[8] = {k0v.x,k0v.y,k0v.z,k0v.w,k1v.x,k1v.y,k1v.z,k1v.w};
            #pragma unroll
            for (int i = 0; i < 4; i++)
                #pragma unroll
                for (int j = 0; j < 8; j++)
                    s[i][j] += qv[i] * kv[j];
        }

        #pragma unroll
        for (int i = 0; i < 4; i++) {
            float rm = -1e30f;
            #pragma unroll
            for (int j = 0; j < 8; j++) { s[i][j] *= scale; rm = fmaxf(rm, s[i][j]); }
            #pragma unroll
            for (int off = 1; off < 8; off <<= 1)
                rm = fmaxf(rm, __shfl_xor_sync(0xffffffffu, rm, off));
            float nm = fmaxf(mi[i], rm);
            float rs = 0.0f;
            #pragma unroll
            for (int j = 0; j < 8; j++) { s[i][j] = __expf(s[i][j] - nm); rs += s[i][j]; }
            #pragma unroll
            for (int off = 1; off < 8; off <<= 1)
                rs += __shfl_xor_sync(0xffffffffu, rs, off);
            float f = __expf(mi[i] - nm);
            li[i] = li[i] * f + rs;
            mi[i] = nm;
            #pragma unroll
            for (int j = 0; j < 8; j++) o[i][j] *= f;
        }
        #pragma unroll
        for (int c = 0; c < 8; c++)
            *(float4*)&Ps[(tx8 + c)*132 + ty4] =
                make_float4(s[0][c], s[1][c], s[2][c], s[3][c]);
        __syncthreads();

        #pragma unroll 8
        for (int k = 0; k < 64; k++) {
            float4 p4 = *(const float4*)&Ps[k*132 + ty4];
            float4 v0 = *(const float4*)&Vs[k*68 + tx8];
            float4 v1 = *(const float4*)&Vs[k*68 + tx8 + 4];
            float pv[4] = {p4.x, p4.y, p4.z, p4.w};
            float vv[8] = {v0.x,v0.y,v0.z,v0.w,v1.x,v1.y,v1.z,v1.w};
            #pragma unroll
            for (int i = 0; i < 4; i++)
                #pragma unroll
                for (int j = 0; j < 8; j++)
                    o[i][j] += pv[i] * vv[j];
        }
    }

    int b = bh / HEADS, h = bh - b * HEADS;
    #pragma unroll
    for (int i = 0; i < 4; i++) {
        int pos = q0 + ty4 + i;
        float inv = 1.0f / li[i];
        size_t off = ((size_t)(b*NTOK + pos)) * DIM + h*HD + tx8;
        __align__(16) __nv_bfloat16 hv[8], lv[8];
        #pragma unroll
        for (int j = 0; j < 8; j++) {
            float f = o[i][j] * inv;
            hv[j] = __float2bfloat16(f);
            lv[j] = __float2bfloat16(f - __bfloat162float(hv[j]));
        }
        *(uint4*)&g_ohh[off] = *(uint4*)hv;
        *(uint4*)&g_oll[off] = *(uint4*)lv;
    }
}

// ==================== launcher ====================
extern "C" void kernel_launch(void* const* d_in, const int* in_sizes, int n_in,
                              void* d_out, int out_size)
{
    const float* x      = (const float*)d_in[0];
    const float* w_qkv  = (const float*)d_in[1];
    const float* b_qkv  = (const float*)d_in[2];
    const float* w_proj = (const float*)d_in[3];
    const float* b_proj = (const float*)d_in[4];
    float* out = (float*)d_out;

    void *xh, *xl, *wqh, *wql, *wph, *wpl, *ohh, *oll;
    cudaGetSymbolAddress(&xh,  g_xh);  cudaGetSymbolAddress(&xl,  g_xl);
    cudaGetSymbolAddress(&wqh, g_wqh); cudaGetSymbolAddress(&wql, g_wql);
    cudaGetSymbolAddress(&wph, g_wph); cudaGetSymbolAddress(&wpl, g_wpl);
    cudaGetSymbolAddress(&ohh, g_ohh); cudaGetSymbolAddress(&oll, g_oll);

    cudaFuncSetAttribute(attn_kernel, cudaFuncAttributeMaxDynamicSharedMemorySize,
                         ATTN_SMEM_BYTES);
    cudaFuncSetAttribute(gemm_mma<0>, cudaFuncAttributeMaxDynamicSharedMemorySize,
                         GEMM_SMEM_B);
    cudaFuncSetAttribute(gemm_mma<1>, cudaFuncAttributeMaxDynamicSharedMemorySize,
                         GEMM_SMEM_B);

    split_kernel<<<(MROWS*DIM/4 + 255)/256, 256>>>(
        x, (__nv_bfloat16*)xh, (__nv_bfloat16*)xl, MROWS*DIM/4);
    split_kernel<<<(3*DIM*DIM/4 + 255)/256, 256>>>(
        w_qkv, (__nv_bfloat16*)wqh, (__nv_bfloat16*)wql, 3*DIM*DIM/4);
    split_kernel<<<(DIM*DIM/4 + 255)/256, 256>>>(
        w_proj, (__nv_bfloat16*)wph, (__nv_bfloat16*)wpl, DIM*DIM/4);
    rope_tab_kernel<<<(NTOK*32 + 255)/256, 256>>>();

    // 1) QKV GEMM (mma.sync) + bias + fused RoPE + scatter
    gemm_mma<1><<<dim3(3*DIM/128, MROWS/128), 256, GEMM_SMEM_B>>>(
        (const __nv_bfloat16*)xh, (const __nv_bfloat16*)xl,
        (const __nv_bfloat16*)wqh, (const __nv_bfloat16*)wql,
        b_qkv, nullptr, MROWS, 3*DIM, DIM);

    // 2) attention (fp32), writes bf16 hi/lo O
    attn_kernel<<<dim3(NTOK/128, BHC), 256, ATTN_SMEM_BYTES>>>();

    // 3) output projection (mma.sync) -> d_out
    gemm_mma<0><<<dim3(DIM/128, MROWS/128), 256, GEMM_SMEM_B>>>(
        (const __nv_bfloat16*)ohh, (const __nv_bfloat16*)oll,
        (const __nv_bfloat16*)wph, (const __nv_bfloat16*)wpl,
        b_proj, out, MROWS, DIM, DIM);
}

// round 6
// speedup vs baseline: 3.1616x; 2.5396x over previous
#include <cuda_runtime.h>
#include <cuda_bf16.h>
#include <cuda_fp16.h>
#include <math.h>
#include <stdint.h>

#define DIM   768
#define HEADS 12
#define HD    64
#define B_    2
#define WW    48
#define NTOK  2304
#define BHC   24
#define MROWS 4608

// -------- scratch (device globals; no allocation allowed) --------
__device__ __half g_qh[BHC*NTOK*HD], g_ql[BHC*NTOK*HD];
__device__ __half g_kh[BHC*NTOK*HD], g_kl[BHC*NTOK*HD];
__device__ __half g_vh[BHC*NTOK*HD], g_vl[BHC*NTOK*HD];
__device__ __nv_bfloat16 g_xh[MROWS*DIM],  g_xl[MROWS*DIM];
__device__ __nv_bfloat16 g_wqh[3*DIM*DIM], g_wql[3*DIM*DIM];
__device__ __nv_bfloat16 g_wph[DIM*DIM],   g_wpl[DIM*DIM];
__device__ __nv_bfloat16 g_ohh[MROWS*DIM], g_oll[MROWS*DIM];
__device__ float g_sin[NTOK*32], g_cos[NTOK*32];

// ==================== helpers ====================
__device__ __forceinline__ uint32_t smem_u32(const void* p) {
    uint32_t a;
    asm("{ .reg .u64 t; cvta.to.shared.u64 t, %1; cvt.u32.u64 %0, t; }" : "=r"(a) : "l"(p));
    return a;
}
__device__ __forceinline__ void ldsm4(uint32_t* r, uint32_t addr) {
    asm volatile("ldmatrix.sync.aligned.m8n8.x4.shared.b16 {%0,%1,%2,%3}, [%4];"
                 : "=r"(r[0]), "=r"(r[1]), "=r"(r[2]), "=r"(r[3]) : "r"(addr));
}
__device__ __forceinline__ void ldsm4t(uint32_t* r, uint32_t addr) {
    asm volatile("ldmatrix.sync.aligned.m8n8.x4.trans.shared.b16 {%0,%1,%2,%3}, [%4];"
                 : "=r"(r[0]), "=r"(r[1]), "=r"(r[2]), "=r"(r[3]) : "r"(addr));
}
__device__ __forceinline__ void mma_bf(float* d, const uint32_t* a,
                                       uint32_t b0, uint32_t b1) {
    asm volatile(
        "mma.sync.aligned.m16n8k16.row.col.f32.bf16.bf16.f32 "
        "{%0,%1,%2,%3}, {%4,%5,%6,%7}, {%8,%9}, {%0,%1,%2,%3};"
        : "+f"(d[0]), "+f"(d[1]), "+f"(d[2]), "+f"(d[3])
        : "r"(a[0]), "r"(a[1]), "r"(a[2]), "r"(a[3]), "r"(b0), "r"(b1));
}
__device__ __forceinline__ void mma_fp(float* d, const uint32_t* a,
                                       uint32_t b0, uint32_t b1) {
    asm volatile(
        "mma.sync.aligned.m16n8k16.row.col.f32.f16.f16.f32 "
        "{%0,%1,%2,%3}, {%4,%5,%6,%7}, {%8,%9}, {%0,%1,%2,%3};"
        : "+f"(d[0]), "+f"(d[1]), "+f"(d[2]), "+f"(d[3])
        : "r"(a[0]), "r"(a[1]), "r"(a[2]), "r"(a[3]), "r"(b0), "r"(b1));
}
// fast e^x on FMA/ALU pipes (no MUFU). |rel err| ~1e-7, x clamped >= -80.
__device__ __forceinline__ float fast_exp(float x) {
    x = fmaxf(x, -80.0f);
    float y = fmaf(x, 1.4426950409f, 12582912.0f);   // + 1.5*2^23 (round)
    float z = y - 12582912.0f;                        // n as float
    int   n = __float_as_int(y) - 0x4B400000;         // n as int
    float f = fmaf(x, 1.4426950409f, -z);             // frac in [-0.5,0.5]
    float p = 1.3333558e-3f;
    p = fmaf(p, f, 9.6181291e-3f);
    p = fmaf(p, f, 5.5504109e-2f);
    p = fmaf(p, f, 2.4022651e-1f);
    p = fmaf(p, f, 6.9314718e-1f);
    p = fmaf(p, f, 1.0f);
    return __int_as_float(__float_as_int(p) + (n << 23));
}
__device__ __forceinline__ void split_h2(float a, float b,
                                         uint32_t& hi, uint32_t& lo) {
    __half2 hh = __floats2half2_rn(a, b);
    __half2 ll = __floats2half2_rn(a - __low2float(hh), b - __high2float(hh));
    hi = *(uint32_t*)&hh;
    lo = *(uint32_t*)&ll;
}

// ==================== prep kernels ====================
__global__ void __launch_bounds__(256) split_kernel(
    const float* __restrict__ src, __nv_bfloat16* __restrict__ hi,
    __nv_bfloat16* __restrict__ lo, int n4)
{
    int i = blockIdx.x * 256 + threadIdx.x;
    if (i >= n4) return;
    float4 v = ((const float4*)src)[i];
    float f[4] = {v.x, v.y, v.z, v.w};
    __nv_bfloat16 h[4], l[4];
    #pragma unroll
    for (int j = 0; j < 4; j++) {
        h[j] = __float2bfloat16(f[j]);
        l[j] = __float2bfloat16(f[j] - __bfloat162float(h[j]));
    }
    ((__nv_bfloat162*)hi)[2*i]   = __halves2bfloat162(h[0], h[1]);
    ((__nv_bfloat162*)hi)[2*i+1] = __halves2bfloat162(h[2], h[3]);
    ((__nv_bfloat162*)lo)[2*i]   = __halves2bfloat162(l[0], l[1]);
    ((__nv_bfloat162*)lo)[2*i+1] = __halves2bfloat162(l[2], l[3]);
}

__global__ void __launch_bounds__(256) rope_tab_kernel()
{
    int idx = blockIdx.x * 256 + threadIdx.x;
    if (idx >= NTOK * 32) return;
    int n = idx >> 5, j = idx & 31;
    int axis = j >> 4, p = j & 15;
    int y = n / WW, x = n - y * WW;
    float idxf  = axis ? (float)x : (float)y;
    float coord = 2.0f * ((idxf + 0.5f) / 48.0f) - 1.0f;
    float invp  = exp2f(-(float)p * 0.41524101186092607f);  // 100^(-p/16)
    float sn, cs; sincosf(6.283185307179586f * coord * invp, &sn, &cs);
    g_sin[idx] = sn; g_cos[idx] = cs;
}

// ==================== mma.sync bf16-split GEMM ====================
#define TSTRIDE 40
#define TILE_E  (128*TSTRIDE)
#define GEMM_SMEM_B (8*TILE_E*2)

__device__ __forceinline__ void g2r(uint4* r,
    const __nv_bfloat16* Ah, const __nv_bfloat16* Al,
    const __nv_bfloat16* Bh, const __nv_bfloat16* Bl,
    int bm, int bn, int K, int k0, int tid)
{
    #pragma unroll
    for (int p = 0; p < 2; p++) {
        int id = p * 256 + tid;
        int row = id >> 2, kc = id & 3;
        size_t oA = (size_t)(bm + row) * K + k0 + kc * 8;
        size_t oB = (size_t)(bn + row) * K + k0 + kc * 8;
        r[0+p] = *(const uint4*)&Ah[oA];
        r[2+p] = *(const uint4*)&Al[oA];
        r[4+p] = *(const uint4*)&Bh[oB];
        r[6+p] = *(const uint4*)&Bl[oB];
    }
}
__device__ __forceinline__ void r2s(__nv_bfloat16* sm, const uint4* r,
                                    int tid, int st)
{
    #pragma unroll
    for (int p = 0; p < 2; p++) {
        int id = p * 256 + tid;
        int off = (id >> 2) * TSTRIDE + (id & 3) * 8;
        #pragma unroll
        for (int t = 0; t < 4; t++)
            *(uint4*)&sm[(st*4 + t) * TILE_E + off] = r[t*2 + p];
    }
}

template<int EPI>
__global__ void __launch_bounds__(256, 1) gemm_mma(
    const __nv_bfloat16* __restrict__ Ah, const __nv_bfloat16* __restrict__ Al,
    const __nv_bfloat16* __restrict__ Bh, const __nv_bfloat16* __restrict__ Bl,
    const float* __restrict__ bias, float* __restrict__ C, int M, int N, int K)
{
    extern __shared__ __align__(16) __nv_bfloat16 sm[];
    const uint32_t sbase = smem_u32(sm);
    const int tid = threadIdx.x;
    const int lane = tid & 31, wid = tid >> 5;
    const int wm = wid & 3, wn = wid >> 2;
    const int bm = blockIdx.y * 128, bn = blockIdx.x * 128;
    const int piece = lane >> 3, pr = lane & 7;

    float acc[2][8][4];
    #pragma unroll
    for (int i = 0; i < 2; i++)
        #pragma unroll
        for (int j = 0; j < 8; j++)
            #pragma unroll
            for (int k = 0; k < 4; k++) acc[i][j][k] = 0.0f;

    const int nit = K >> 5;
    uint4 r[8];
    g2r(r, Ah, Al, Bh, Bl, bm, bn, K, 0, tid);
    r2s(sm, r, tid, 0);
    __syncthreads();

    const int arow = wm*32 + (piece & 1)*8 + pr;
    const int brow = wn*64 + (piece & 1)*8 + pr;
    const int kofp = (piece >> 1) * 8;

    for (int it = 0; it < nit; it++) {
        int st = it & 1;
        bool more = (it + 1) < nit;
        if (more) g2r(r, Ah, Al, Bh, Bl, bm, bn, K, (it + 1) << 5, tid);

        uint32_t tA = sbase + (uint32_t)(st*4) * (TILE_E*2);
        #pragma unroll
        for (int ks = 0; ks < 2; ks++) {
            int koff = ks*16 + kofp;
            uint32_t ah[2][4], al[2][4];
            #pragma unroll
            for (int mt = 0; mt < 2; mt++) {
                uint32_t ad = tA + ((arow + mt*16) * TSTRIDE + koff) * 2;
                ldsm4(ah[mt], ad);
                ldsm4(al[mt], ad + TILE_E*2);
            }
            #pragma unroll
            for (int np = 0; np < 4; np++) {
                uint32_t bd = tA + 2*(TILE_E*2)
                            + ((brow + np*16) * TSTRIDE + koff) * 2;
                uint32_t bh[4], bl[4];
                ldsm4(bh, bd);
                ldsm4(bl, bd + TILE_E*2);
                #pragma unroll
                for (int mt = 0; mt < 2; mt++) {
                    mma_bf(acc[mt][np*2],   ah[mt], bh[0], bh[2]);
                    mma_bf(acc[mt][np*2+1], ah[mt], bh[1], bh[3]);
                    mma_bf(acc[mt][np*2],   ah[mt], bl[0], bl[2]);
                    mma_bf(acc[mt][np*2+1], ah[mt], bl[1], bl[3]);
                    mma_bf(acc[mt][np*2],   al[mt], bh[0], bh[2]);
                    mma_bf(acc[mt][np*2+1], al[mt], bh[1], bh[3]);
                }
            }
        }
        __syncthreads();
        if (more) {
            r2s(sm, r, tid, st ^ 1);
            __syncthreads();
        }
    }

    const int cbase = bn + wn * 64;
    if (EPI == 0) {
        #pragma unroll
        for (int mt = 0; mt < 2; mt++)
            #pragma unroll
            for (int half = 0; half < 2; half++) {
                int m = bm + wm*32 + mt*16 + (lane >> 2) + half*8;
                #pragma unroll
                for (int nt = 0; nt < 8; nt++) {
                    int c = cbase + nt*8 + (lane & 3)*2;
                    float2 v;
                    v.x = acc[mt][nt][half*2+0] + bias[c];
                    v.y = acc[mt][nt][half*2+1] + bias[c+1];
                    *(float2*)&C[(size_t)m * N + c] = v;
                }
            }
    } else {
        // QKV epilogue: bias + RoPE(q,k) + q-prescale + fp16 hi/lo scatter
        int which = cbase / DIM;
        int h = (cbase % DIM) >> 6;
        __half* bhp = (which == 0) ? g_qh : (which == 1) ? g_kh : g_vh;
        __half* blp = (which == 0) ? g_ql : (which == 1) ? g_kl : g_vl;
        const float qs = (which == 0) ? 0.125f : 1.0f;
        #pragma unroll
        for (int mt = 0; mt < 2; mt++)
            #pragma unroll
            for (int half = 0; half < 2; half++) {
                int m = bm + wm*32 + mt*16 + (lane >> 2) + half*8;
                int bb = m / NTOK, pos = m - bb * NTOK;
                size_t dof = ((size_t)(bb*HEADS + h) * NTOK + pos) * HD;
                __half* dsth = bhp + dof;
                __half* dstl = blp + dof;
                if (which < 2) {
                    #pragma unroll
                    for (int nt = 0; nt < 4; nt++) {
                        int d0 = nt*8 + (lane & 3)*2;
                        float rl[2], rh[2];
                        #pragma unroll
                        for (int j = 0; j < 2; j++) {
                            float vlo = acc[mt][nt][half*2+j]   + bias[cbase + d0 + j];
                            float vhi = acc[mt][nt+4][half*2+j] + bias[cbase + 32 + d0 + j];
                            float sn = g_sin[pos*32 + d0 + j];
                            float cs = g_cos[pos*32 + d0 + j];
                            rl[j] = (vlo*cs - vhi*sn) * qs;
                            rh[j] = (vhi*cs + vlo*sn) * qs;
                        }
                        uint32_t hh, ll;
                        split_h2(rl[0], rl[1], hh, ll);
                        *(uint32_t*)&dsth[d0] = hh; *(uint32_t*)&dstl[d0] = ll;
                        split_h2(rh[0], rh[1], hh, ll);
                        *(uint32_t*)&dsth[32 + d0] = hh; *(uint32_t*)&dstl[32 + d0] = ll;
                    }
                } else {
                    #pragma unroll
                    for (int nt = 0; nt < 8; nt++) {
                        int d = nt*8 + (lane & 3)*2;
                        float v0 = acc[mt][nt][half*2+0] + bias[cbase + d];
                        float v1 = acc[mt][nt][half*2+1] + bias[cbase + d + 1];
                        uint32_t hh, ll;
                        split_h2(v0, v1, hh, ll);
                        *(uint32_t*)&dsth[d] = hh; *(uint32_t*)&dstl[d] = ll;
                    }
                }
            }
    }
}

// ==================== attention: HMMA fp16-split flash ====================
// Grid (18, 24), 256 thr (8 warps x 16 q-rows). 64-key tiles.
// Smem 36864B: Q staging (128x72 hi+lo fp16) reused as K/V tile buffer.
#define AST 72
#define ATTN_SMEM (128*AST*2*2)   // 36864 bytes

__global__ void __launch_bounds__(256, 2) attn_mma()
{
    extern __shared__ __align__(16) __half smh[];
    const uint32_t sb = smem_u32(smh);
    __half* sQh = smh;  __half* sQl = smh + 128*AST;
    __half* sKh = smh;  __half* sKl = smh + 64*AST;
    __half* sVh = smh + 2*64*AST;  __half* sVl = smh + 3*64*AST;

    const int tid = threadIdx.x;
    const int lane = tid & 31, w = tid >> 5;
    const int l15 = lane & 15, l16 = lane >> 4;
    const int bh = blockIdx.y, q0 = blockIdx.x * 128;

    const __half* Qh = g_qh + ((size_t)bh * NTOK + q0) * HD;
    const __half* Ql = g_ql + ((size_t)bh * NTOK + q0) * HD;
    const __half* Kh = g_kh + (size_t)bh * NTOK * HD;
    const __half* Kl = g_kl + (size_t)bh * NTOK * HD;
    const __half* Vh = g_vh + (size_t)bh * NTOK * HD;
    const __half* Vl = g_vl + (size_t)bh * NTOK * HD;

    // ---- stage Q (hi/lo), move to A-fragments, then free the buffer ----
    #pragma unroll
    for (int t = 0; t < 8; t++) {
        int lin = t * 256 + tid;
        int arr = lin >> 10, rem = lin & 1023;
        int row = rem >> 3, c = (rem & 7) * 8;
        const __half* src = (arr ? Ql : Qh) + (size_t)row * HD + c;
        __half* dst = (arr ? sQl : sQh) + row * AST + c;
        *(uint4*)dst = *(const uint4*)src;
    }
    __syncthreads();
    uint32_t qfh[4][4], qfl[4][4];
    {
        uint32_t qa = sb + (((w*16 + l15) * AST) + l16*8) * 2;
        #pragma unroll
        for (int ks = 0; ks < 4; ks++) {
            ldsm4(qfh[ks], qa + ks*32);
            ldsm4(qfl[ks], qa + ks*32 + 128*AST*2);
        }
    }

    float acc[8][4];
    #pragma unroll
    for (int i = 0; i < 8; i++)
        #pragma unroll
        for (int j = 0; j < 4; j++) acc[i][j] = 0.0f;
    float m0 = -1e30f, m1 = -1e30f, l0 = 0.0f, l1 = 0.0f;

    const uint32_t kbase = sb + (l15 * AST + l16*8) * 2;
    const uint32_t vbase = sb + 2*64*AST*2 + (l15 * AST + l16*8) * 2;

    for (int t = 0; t < NTOK/64; t++) {
        const int k0 = t * 64;
        uint4 rv[8];
        #pragma unroll
        for (int i = 0; i < 8; i++) {
            int lin = i * 256 + tid;
            int arr = lin >> 9, rem = lin & 511;
            int row = rem >> 3, c = (rem & 7) * 8;
            const __half* src = (arr == 0 ? Kh : arr == 1 ? Kl : arr == 2 ? Vh : Vl)
                                + (size_t)(k0 + row) * HD + c;
            rv[i] = *(const uint4*)src;
        }
        __syncthreads();   // prior readers done (iter0: Q ldmatrix done)
        #pragma unroll
        for (int i = 0; i < 8; i++) {
            int lin = i * 256 + tid;
            int arr = lin >> 9, rem = lin & 511;
            int row = rem >> 3, c = (rem & 7) * 8;
            __half* dst = (arr == 0 ? sKh : arr == 1 ? sKl : arr == 2 ? sVh : sVl)
                          + row * AST + c;
            *(uint4*)dst = rv[i];
        }
        __syncthreads();

        // ---- S = Q K^T (warp: 16 x 64) ----
        float s[8][4];
        #pragma unroll
        for (int i = 0; i < 8; i++)
            #pragma unroll
            for (int j = 0; j < 4; j++) s[i][j] = 0.0f;
        #pragma unroll
        for (int ks = 0; ks < 4; ks++) {
            #pragma unroll
            for (int nbp = 0; nbp < 8; nbp += 2) {
                uint32_t kh4[4], kl4[4];
                uint32_t ka = kbase + (nbp*8*AST + ks*16) * 2;
                ldsm4(kh4, ka);
                ldsm4(kl4, ka + 64*AST*2);
                mma_fp(s[nbp],   qfh[ks], kh4[0], kh4[2]);
                mma_fp(s[nbp+1], qfh[ks], kh4[1], kh4[3]);
                mma_fp(s[nbp],   qfl[ks], kh4[0], kh4[2]);
                mma_fp(s[nbp+1], qfl[ks], kh4[1], kh4[3]);
                mma_fp(s[nbp],   qfh[ks], kl4[0], kl4[2]);
                mma_fp(s[nbp+1], qfh[ks], kl4[1], kl4[3]);
            }
        }

        // ---- online softmax (rows: c0,c1 -> r; c2,c3 -> r+8) ----
        float mx0 = -1e30f, mx1 = -1e30f;
        #pragma unroll
        for (int i = 0; i < 8; i++) {
            mx0 = fmaxf(mx0, fmaxf(s[i][0], s[i][1]));
            mx1 = fmaxf(mx1, fmaxf(s[i][2], s[i][3]));
        }
        mx0 = fmaxf(mx0, __shfl_xor_sync(0xffffffffu, mx0, 1));
        mx0 = fmaxf(mx0, __shfl_xor_sync(0xffffffffu, mx0, 2));
        mx1 = fmaxf(mx1, __shfl_xor_sync(0xffffffffu, mx1, 1));
        mx1 = fmaxf(mx1, __shfl_xor_sync(0xffffffffu, mx1, 2));
        float nm0 = fmaxf(m0, mx0), nm1 = fmaxf(m1, mx1);
        float f0 = fast_exp(m0 - nm0), f1 = fast_exp(m1 - nm1);
        m0 = nm0; m1 = nm1;
        float sum0 = 0.0f, sum1 = 0.0f;
        #pragma unroll
        for (int i = 0; i < 8; i++) {
            s[i][0] = fast_exp(s[i][0] - nm0); sum0 += s[i][0];
            s[i][1] = fast_exp(s[i][1] - nm0); sum0 += s[i][1];
            s[i][2] = fast_exp(s[i][2] - nm1); sum1 += s[i][2];
            s[i][3] = fast_exp(s[i][3] - nm1); sum1 += s[i][3];
        }
        sum0 += __shfl_xor_sync(0xffffffffu, sum0, 1);
        sum0 += __shfl_xor_sync(0xffffffffu, sum0, 2);
        sum1 += __shfl_xor_sync(0xffffffffu, sum1, 1);
        sum1 += __shfl_xor_sync(0xffffffffu, sum1, 2);
        l0 = l0 * f0 + sum0;
        l1 = l1 * f1 + sum1;
        #pragma unroll
        for (int i = 0; i < 8; i++) {
            acc[i][0] *= f0; acc[i][1] *= f0;
            acc[i][2] *= f1; acc[i][3] *= f1;
        }

        // ---- P -> fp16 hi/lo A-fragments (register-only) ----
        uint32_t aph[4][4], apl[4][4];
        #pragma unroll
        for (int ks = 0; ks < 4; ks++) {
            int n0 = 2*ks, n1 = 2*ks + 1;
            split_h2(s[n0][0], s[n0][1], aph[ks][0], apl[ks][0]);
            split_h2(s[n0][2], s[n0][3], aph[ks][1], apl[ks][1]);
            split_h2(s[n1][0], s[n1][1], aph[ks][2], apl[ks][2]);
            split_h2(s[n1][2], s[n1][3], aph[ks][3], apl[ks][3]);
        }

        // ---- O += P V (warp: 16 x 64) ----
        #pragma unroll
        for (int ks = 0; ks < 4; ks++) {
            #pragma unroll
            for (int nbp = 0; nbp < 8; nbp += 2) {
                uint32_t vh4[4], vl4[4];
                uint32_t va = vbase + (ks*16*AST + nbp*8) * 2;
                ldsm4t(vh4, va);
                ldsm4t(vl4, va + 64*AST*2);
                mma_fp(acc[nbp],   aph[ks], vh4[0], vh4[1]);
                mma_fp(acc[nbp+1], aph[ks], vh4[2], vh4[3]);
                mma_fp(acc[nbp],   apl[ks], vh4[0], vh4[1]);
                mma_fp(acc[nbp+1], apl[ks], vh4[2], vh4[3]);
                mma_fp(acc[nbp],   aph[ks], vl4[0], vl4[1]);
                mma_fp(acc[nbp+1], aph[ks], vl4[2], vl4[3]);
            }
        }
    }

    // ---- normalize + write O as bf16 hi/lo, [b, n, h*64 + d] ----
    float inv0 = 1.0f / l0, inv1 = 1.0f / l1;
    int b = bh / HEADS, h = bh - b * HEADS;
    int r0 = q0 + w*16 + (lane >> 2);
    int col = h*HD + (lane & 3)*2;
    #pragma unroll
    for (int nb = 0; nb < 8; nb++) {
        size_t o0 = ((size_t)(b*NTOK + r0))     * DIM + col + nb*8;
        size_t o1 = ((size_t)(b*NTOK + r0 + 8)) * DIM + col + nb*8;
        float a0 = acc[nb][0]*inv0, a1 = acc[nb][1]*inv0;
        float a2 = acc[nb][2]*inv1, a3 = acc[nb][3]*inv1;
        __nv_bfloat162 hh, ll;
        hh = __floats2bfloat162_rn(a0, a1);
        ll = __floats2bfloat162_rn(a0 - __bfloat162float(hh.x),
                                   a1 - __bfloat162float(hh.y));
        *(__nv_bfloat162*)&g_ohh[o0] = hh;
        *(__nv_bfloat162*)&g_oll[o0] = ll;
        hh = __floats2bfloat162_rn(a2, a3);
        ll = __floats2bfloat162_rn(a2 - __bfloat162float(hh.x),
                                   a3 - __bfloat162float(hh.y));
        *(__nv_bfloat162*)&g_ohh[o1] = hh;
        *(__nv_bfloat162*)&g_oll[o1] = ll;
    }
}

// ==================== launcher ====================
extern "C" void kernel_launch(void* const* d_in, const int* in_sizes, int n_in,
                              void* d_out, int out_size)
{
    const float* x      = (const float*)d_in[0];
    const float* w_qkv  = (const float*)d_in[1];
    const float* b_qkv  = (const float*)d_in[2];
    const float* w_proj = (const float*)d_in[3];
    const float* b_proj = (const float*)d_in[4];
    float* out = (float*)d_out;

    void *xh, *xl, *wqh, *wql, *wph, *wpl, *ohh, *oll;
    cudaGetSymbolAddress(&xh,  g_xh);  cudaGetSymbolAddress(&xl,  g_xl);
    cudaGetSymbolAddress(&wqh, g_wqh); cudaGetSymbolAddress(&wql, g_wql);
    cudaGetSymbolAddress(&wph, g_wph); cudaGetSymbolAddress(&wpl, g_wpl);
    cudaGetSymbolAddress(&ohh, g_ohh); cudaGetSymbolAddress(&oll, g_oll);

    cudaFuncSetAttribute(gemm_mma<0>, cudaFuncAttributeMaxDynamicSharedMemorySize,
                         GEMM_SMEM_B);
    cudaFuncSetAttribute(gemm_mma<1>, cudaFuncAttributeMaxDynamicSharedMemorySize,
                         GEMM_SMEM_B);

    split_kernel<<<(MROWS*DIM/4 + 255)/256, 256>>>(
        x, (__nv_bfloat16*)xh, (__nv_bfloat16*)xl, MROWS*DIM/4);
    split_kernel<<<(3*DIM*DIM/4 + 255)/256, 256>>>(
        w_qkv, (__nv_bfloat16*)wqh, (__nv_bfloat16*)wql, 3*DIM*DIM/4);
    split_kernel<<<(DIM*DIM/4 + 255)/256, 256>>>(
        w_proj, (__nv_bfloat16*)wph, (__nv_bfloat16*)wpl, DIM*DIM/4);
    rope_tab_kernel<<<(NTOK*32 + 255)/256, 256>>>();

    // 1) QKV GEMM + bias + RoPE + fp16 hi/lo scatter
    gemm_mma<1><<<dim3(3*DIM/128, MROWS/128), 256, GEMM_SMEM_B>>>(
        (const __nv_bfloat16*)xh, (const __nv_bfloat16*)xl,
        (const __nv_bfloat16*)wqh, (const __nv_bfloat16*)wql,
        b_qkv, nullptr, MROWS, 3*DIM, DIM);

    // 2) attention (HMMA fp16-split flash)
    attn_mma<<<dim3(NTOK/128, BHC), 256, ATTN_SMEM>>>();

    // 3) output projection -> d_out
    gemm_mma<0><<<dim3(DIM/128, MROWS/128), 256, GEMM_SMEM_B>>>(
        (const __nv_bfloat16*)ohh, (const __nv_bfloat16*)oll,
        (const __nv_bfloat16*)wph, (const __nv_bfloat16*)wpl,
        b_proj, out, MROWS, DIM, DIM);
}